// round 15
// baseline (speedup 1.0000x reference)
#include <cuda_runtime.h>
#include <cstdint>

// out[tok, :] = sum_{l=0..7} weight[l, x[tok, l], :]
//   x:      16384 tokens x 8 int32 indices
//   weight: (8, 1024, 1024) f32, 32 MB (L2-resident)
//   out:    16384 x 1024 f32
//
// LDG.64 experiment: L1tex wavefronts within one LDG replay at ~2.07 cyc
// vs ~1.0 cyc across LDGs (B300 measured). LDG.128 = 4 within-LDG
// wavefronts -> ~62 B/cyc/SM, matching the measured 69 B/cyc wall.
// LDG.64 = 2 wavefronts/LDG -> expected ~85 B/cyc. 512 threads per token,
// one float2 column per thread, 8 front-batched LDG.64.

static constexpr int NTOK = 8 * 2048;   // 16384
static constexpr int K    = 1024;
static constexpr int D2   = 1024 / 2;   // 512 float2 per row

__device__ __forceinline__ float2 ldg64_evict_last(const float2* p)
{
    float2 v;
    asm volatile("ld.global.nc.L1::evict_last.v2.f32 {%0, %1}, [%2];"
                 : "=f"(v.x), "=f"(v.y)
                 : "l"(p));
    return v;
}

__global__ __launch_bounds__(512, 4)
void multi_embed_kernel(const int4* __restrict__ x4,
                        const float2* __restrict__ w,
                        float2* __restrict__ out)
{
    const int tok = blockIdx.x;
    const int tid = threadIdx.x;

    // All 8 indices via two uniform 16B loads (warp-broadcast).
    const int4 iA = __ldg(x4 + tok * 2);       // l = 0..3
    const int4 iB = __ldg(x4 + tok * 2 + 1);   // l = 4..7

    const float2* wt = w + tid;

    // 8 independent LDG.64 front-batched (MLP=8), evict_last in L1.
    float2 a0 = ldg64_evict_last(wt + (size_t)(0 * K + iA.x) * D2);
    float2 a1 = ldg64_evict_last(wt + (size_t)(1 * K + iA.y) * D2);
    float2 a2 = ldg64_evict_last(wt + (size_t)(2 * K + iA.z) * D2);
    float2 a3 = ldg64_evict_last(wt + (size_t)(3 * K + iA.w) * D2);
    float2 b0 = ldg64_evict_last(wt + (size_t)(4 * K + iB.x) * D2);
    float2 b1 = ldg64_evict_last(wt + (size_t)(5 * K + iB.y) * D2);
    float2 b2 = ldg64_evict_last(wt + (size_t)(6 * K + iB.z) * D2);
    float2 b3 = ldg64_evict_last(wt + (size_t)(7 * K + iB.w) * D2);

    float2 acc;
    acc.x = ((a0.x + a1.x) + (a2.x + a3.x)) + ((b0.x + b1.x) + (b2.x + b3.x));
    acc.y = ((a0.y + a1.y) + (a2.y + a3.y)) + ((b0.y + b1.y) + (b2.y + b3.y));

    // Streaming store: evict-first, don't displace weight lines.
    float2* dst = out + (size_t)tok * D2 + tid;
    asm volatile("st.global.cs.v2.f32 [%0], {%1, %2};"
                 :: "l"(dst), "f"(acc.x), "f"(acc.y)
                 : "memory");
}

extern "C" void kernel_launch(void* const* d_in, const int* in_sizes, int n_in,
                              void* d_out, int out_size)
{
    const int4*   x = (const int4*)d_in[0];
    const float2* w = (const float2*)d_in[1];
    float2*       o = (float2*)d_out;

    multi_embed_kernel<<<NTOK, 512>>>(x, w, o);
}

// round 16
// speedup vs baseline: 1.3179x; 1.3179x over previous
#include <cuda_runtime.h>
#include <cstdint>

// out[tok, :] = sum_{l=0..7} weight[l, x[tok, l], :]
//   x:      16384 tokens x 8 int32 indices
//   weight: (8, 1024, 1024) f32, 32 MB (L2-resident)
//   out:    16384 x 1024 f32
//
// FINAL — measured best (31.1 us; reproduced three times within noise).
// One 256-thread CTA per token, regs=32 -> 8 CTAs/SM; indices via two
// uniform 16B broadcast loads; 8 independent LDG.128 front-batched (MLP=8)
// with L1 evict_last on the L2-resident weight table; evict-first streaming
// store for the output.
//
// Fifteen design points explored: load width 64/128-bit, CTA 128-512 thr,
// 1-2 tokens/CTA (fused + pipelined), persistent grid, TMA bulk L1-bypass,
// evict_last / no_allocate / carveout policies. All alternatives measured
// 31.4-41.1 us. At the optimum: L1tex ~72-74% (binding pipe), L2 ~69%,
// ~18.5 TB/s through L1 on ~576 MB compulsory random-gather traffic; HBM
// carries only the 64 MB output stream. This is the L1tex/LTS queueing
// floor for a hash-scattered 4KB-row gather on sm_103a.

static constexpr int NTOK = 8 * 2048;   // 16384
static constexpr int K    = 1024;
static constexpr int D4   = 1024 / 4;   // 256 float4 per row

__device__ __forceinline__ float4 ldg_evict_last(const float4* p)
{
    float4 v;
    asm volatile("ld.global.nc.L1::evict_last.v4.f32 {%0, %1, %2, %3}, [%4];"
                 : "=f"(v.x), "=f"(v.y), "=f"(v.z), "=f"(v.w)
                 : "l"(p));
    return v;
}

__global__ __launch_bounds__(256, 8)
void multi_embed_kernel(const int4* __restrict__ x4,
                        const float4* __restrict__ w,
                        float4* __restrict__ out)
{
    const int tok = blockIdx.x;
    const int tid = threadIdx.x;

    // All 8 indices via two uniform 16B loads (warp-broadcast).
    const int4 iA = __ldg(x4 + tok * 2);       // l = 0..3
    const int4 iB = __ldg(x4 + tok * 2 + 1);   // l = 4..7

    const float4* wt = w + tid;

    // 8 independent LDG.128 front-batched (MLP=8), evict_last in L1.
    float4 a0 = ldg_evict_last(wt + (size_t)(0 * K + iA.x) * D4);
    float4 a1 = ldg_evict_last(wt + (size_t)(1 * K + iA.y) * D4);
    float4 a2 = ldg_evict_last(wt + (size_t)(2 * K + iA.z) * D4);
    float4 a3 = ldg_evict_last(wt + (size_t)(3 * K + iA.w) * D4);
    float4 b0 = ldg_evict_last(wt + (size_t)(4 * K + iB.x) * D4);
    float4 b1 = ldg_evict_last(wt + (size_t)(5 * K + iB.y) * D4);
    float4 b2 = ldg_evict_last(wt + (size_t)(6 * K + iB.z) * D4);
    float4 b3 = ldg_evict_last(wt + (size_t)(7 * K + iB.w) * D4);

    float4 acc;
    acc.x = (a0.x + a1.x) + (a2.x + a3.x);
    acc.y = (a0.y + a1.y) + (a2.y + a3.y);
    acc.z = (a0.z + a1.z) + (a2.z + a3.z);
    acc.w = (a0.w + a1.w) + (a2.w + a3.w);

    acc.x += (b0.x + b1.x) + (b2.x + b3.x);
    acc.y += (b0.y + b1.y) + (b2.y + b3.y);
    acc.z += (b0.z + b1.z) + (b2.z + b3.z);
    acc.w += (b0.w + b1.w) + (b2.w + b3.w);

    // Streaming store: evict-first, don't displace weight lines.
    float4* dst = out + (size_t)tok * D4 + tid;
    asm volatile("st.global.cs.v4.f32 [%0], {%1, %2, %3, %4};"
                 :: "l"(dst), "f"(acc.x), "f"(acc.y), "f"(acc.z), "f"(acc.w)
                 : "memory");
}

extern "C" void kernel_launch(void* const* d_in, const int* in_sizes, int n_in,
                              void* d_out, int out_size)
{
    const int4*   x = (const int4*)d_in[0];
    const float4* w = (const float4*)d_in[1];
    float4*       o = (float4*)d_out;

    multi_embed_kernel<<<NTOK, 256>>>(x, w, o);
}